// round 17
// baseline (speedup 1.0000x reference)
#include <cuda_runtime.h>
#include <cuda_fp16.h>
#include <cstdint>

// CARAFE: B=8, C=256, H=W=64, K=5, UP=2.
// out[b,c,2h+i,2w+j] = sum_{ki,kj} km[b,(i*2+j)*25+ki*5+kj,h,w] * x[b,c,h+ki-2,w+kj-2]
//
// R16 = R13's channel-paired dataflow (best, 50.2us) minus its ~100 PRMT/unit
// weight broadcasts:
//  - weights pre-DUPLICATED per tap: wd[100] half2 regs, zero broadcast instrs
//  - registers for that reclaimed from staging: cp.async fp32 (zero-fill) ->
//    3-deep fp32 smem ring -> per-iter convert pass -> 2-deep fp16 ring of
//    channel-paired (c0,c1) half2 planes
//  - 2 fp16 chains (taps 0-12 / 13-24), cross-chain combine fully in fp32
// Inner loop per channel-pair: 25 LDS.32 + 100 HFMA2, nothing else.
// Schedule: 592 CTAs single wave, 28/27 static split, <=2 constant-bh
// segments, 2x64-thread independent groups, named barriers.

namespace {
constexpr int Hc = 64, Wc = 64;
constexpr int QQ = 100;
constexpr int THREADS = 128;
constexpr int CH4 = Hc * Wc / 4;            // 1024 float4 per channel image
constexpr int SROWH = 72;                   // half2 per staged row (4+64+4)
constexpr int PAIRH = 5 * SROWH;            // 360 half2 per pair-plane
constexpr int HBUF  = 2 * PAIRH;            // 720 half2 per fp16 buffer
constexpr int NHB   = 2;
constexpr int F32BUF = 4 * 5 * 64;          // 1280 floats per fp32 buffer
constexpr int F32BYTES = F32BUF * 4;        // 5120
constexpr int NFB   = 3;
constexpr int NUNITS = 512 * 32;            // 16384
constexpr int NCTA = 592;                   // single wave
constexpr int NBIG = NUNITS - NCTA * 27;    // 400 CTAs take 28 units
constexpr int U4 = 8 * CH4;                 // float4 stride of one unit (8 ch)
}

__device__ __forceinline__ void cp_async16(uint32_t dst, const float4* src, bool valid) {
    int sz = valid ? 16 : 0;
    asm volatile("cp.async.cg.shared.global [%0], [%1], 16, %2;"
                 :: "r"(dst), "l"(src), "r"(sz) : "memory");
}
__device__ __forceinline__ void cp_commit() {
    asm volatile("cp.async.commit_group;" ::: "memory");
}
template <int N>
__device__ __forceinline__ void cp_wait() {
    asm volatile("cp.async.wait_group %0;" :: "n"(N) : "memory");
}
__device__ __forceinline__ void group_bar(int id) {
    asm volatile("bar.sync %0, 64;" :: "r"(id) : "memory");
}
__device__ __forceinline__ uint32_t pack_h2u(float lo, float hi) {
    uint32_t r;   // low <- lo, high <- hi
    asm("cvt.rn.f16x2.f32 %0, %1, %2;" : "=r"(r) : "f"(hi), "f"(lo));
    return r;
}
__device__ __forceinline__ __half2 dup_h2(float v) {
    uint32_t r;
    asm("cvt.rn.f16x2.f32 %0, %1, %1;" : "=r"(r) : "f"(v));
    return *reinterpret_cast<__half2*>(&r);
}

__global__ __launch_bounds__(THREADS, 4)
void carafe_kernel(const float* __restrict__ x,
                   const float* __restrict__ km,
                   float* __restrict__ out)
{
    const int tid = threadIdx.x;
    const int g   = tid >> 6;            // independent 64-thread group 0/1
    const int w   = tid & 63;            // pixel column / lane within group

    // per-group fp32 staging ring + fp16 compute ring
    __shared__ __align__(16) float   sf32[2 * NFB * F32BUF];   // 30720 B
    __shared__ __align__(16) __half2 sf16[2 * NHB * HBUF];     // 11520 B

    float*   f32g = sf32 + g * (NFB * F32BUF);
    __half2* f16g = sf16 + g * (NHB * HBUF);
    const uint32_t f32_u32 = (uint32_t)__cvta_generic_to_shared(f32g);

    // ---- static work range ----
    const int cta   = blockIdx.x;
    const int n     = (cta < NBIG) ? 28 : 27;
    const int start = (cta < NBIG) ? cta * 28 : 27 * cta + NBIG;

    // ---- zero halo cols (0..3, 68..71) of both fp16 buffers, once ----
    for (int e = w; e < NHB * 2 * 5 * 8; e += 64) {
        int rc = e >> 3, cs = e & 7;
        int col = (cs < 4) ? cs : (64 + cs);
        f16g[rc * SROWH + col] = __half2half2(__float2half(0.f));
    }

    // ---- whole-kernel task constants ----
    // cp.async tasks k=0..4: e = w + 64k (0..319): gc=e/80, r=(e%80)/16, c4=e%16
    int tR[5], tSrcC[5];     // row-within-window, (gc*CH4 + c4)
    uint32_t tDstB[5];       // byte offset within fp32 buffer
    #pragma unroll
    for (int k = 0; k < 5; k++) {
        int e  = w + 64 * k;
        int gc = e / 80, rem = e % 80;
        int r  = rem >> 4, c4 = rem & 15;
        tR[k]    = r;
        tSrcC[k] = gc * CH4 + c4;
        tDstB[k] = (uint32_t)(((gc * 5 + r) * 64 + 4 * c4) * 4);
    }
    // convert tasks k=0..2: t = w + 64k, active t<160: p=t/80, r=(t%80)/16, c4=t%16
    int cSrcA[3], cDst[3]; bool cAct[3];
    #pragma unroll
    for (int k = 0; k < 3; k++) {
        int t = w + 64 * k;
        cAct[k] = (t < 160);
        int tt = cAct[k] ? t : 0;
        int p = tt / 80, rem = tt % 80;
        int r = rem >> 4, c4 = rem & 15;
        cSrcA[k] = ((2 * p) * 5 + r) * 64 + 4 * c4;
        cDst[k]  = (p * 5 + r) * SROWH + 4 + 4 * c4;
    }

    const float4* x4 = (const float4*)x;

    int u = start, rem = n;
    bool first = true;

    #pragma unroll 1
    while (rem > 0) {
        const int bh = u >> 5;
        const int g0 = u & 31;
        const int b  = bh >> 6;
        const int h  = bh & 63;
        int cnt = 32 - g0; if (cnt > rem) cnt = rem;

        if (!first) group_bar(g + 1);   // prev segment's readers done
        first = false;

        const int base4 = ((b << 8) + (g0 << 3) + (g << 2)) * CH4;

        // ---- cp.async issue for one unit into fp32 buffer fb ----
        auto issue = [&](int b4, int fb) {
            uint32_t d = f32_u32 + (uint32_t)fb * F32BYTES;
            #pragma unroll
            for (int k = 0; k < 5; k++) {
                int  gr = h - 2 + tR[k];
                bool v  = (unsigned)gr < (unsigned)Hc;
                int  src = b4 + tSrcC[k] + (v ? gr : 0) * 16;
                cp_async16(d + tDstB[k], x4 + src, v);
            }
            cp_commit();
        };

        // prologue: units 0 (+1)
        issue(base4, 0);
        if (cnt > 1) issue(base4 + U4, 1);

        // ---- weights for this bh: DUPLICATED per tap, 100 half2 regs ----
        const float* kmp = km + ((size_t)b * QQ * Hc + h) * Wc + w;
        __half2 wd[QQ];
        #pragma unroll
        for (int q = 0; q < QQ; q++)
            wd[q] = dup_h2(__ldg(kmp + (size_t)q * (Hc * Wc)));

        float* optr = out + ((size_t)((b << 8) + (g0 << 3) + (g << 2)) * 128
                             + 2 * h) * 128 + 2 * w;
        int rdF = 0;
        int b4n = base4 + 2 * U4;

        #pragma unroll 1
        for (int j = 0; j < cnt; j++) {
            if (j + 1 < cnt) cp_wait<1>(); else cp_wait<0>();
            group_bar(g + 1);   // fp32[rdF] complete; fp16 readers of j-1 done

            // ---- convert fp32[rdF] -> fp16[(j&1)] channel-paired (c_even,c_odd) ----
            const float* fs = f32g + rdF * F32BUF;
            __half2*     hd = f16g + (j & 1) * HBUF;
            #pragma unroll
            for (int k = 0; k < 3; k++) {
                if (cAct[k]) {
                    float4 a  = *reinterpret_cast<const float4*>(fs + cSrcA[k]);
                    float4 bb = *reinterpret_cast<const float4*>(fs + cSrcA[k] + 320);
                    uint4 s;
                    s.x = pack_h2u(a.x, bb.x); s.y = pack_h2u(a.y, bb.y);
                    s.z = pack_h2u(a.z, bb.z); s.w = pack_h2u(a.w, bb.w);
                    *reinterpret_cast<uint4*>(hd + cDst[k]) = s;
                }
            }

            // ---- issue unit j+2 into the fp32 buffer convert(j-1) released ----
            if (j + 2 < cnt) {
                int wf = rdF + 2; if (wf >= NFB) wf -= NFB;
                issue(b4n, wf);
                b4n += U4;
            }
            group_bar(g + 1);   // fp16[(j&1)] visible to all group threads

            // ---- compute 2 channel-pairs: 25 LDS.32 + 100 HFMA2 each ----
            #pragma unroll
            for (int pp = 0; pp < 2; pp++) {
                const __half2* sp = hd + pp * PAIRH + (w + 2);
                const __half2 z = __half2half2(__float2half(0.f));
                __half2 A0=z, A1=z, A2=z, A3=z;   // taps 0..12
                __half2 B0=z, B1=z, B2=z, B3=z;   // taps 13..24

                #pragma unroll
                for (int k = 0; k < 25; k++) {
                    __half2 xk = sp[(k / 5) * SROWH + (k % 5)];   // (c0,c1)
                    if (k < 13) {
                        A0 = __hfma2(wd[k],      xk, A0);
                        A1 = __hfma2(wd[25 + k], xk, A1);
                        A2 = __hfma2(wd[50 + k], xk, A2);
                        A3 = __hfma2(wd[75 + k], xk, A3);
                    } else {
                        B0 = __hfma2(wd[k],      xk, B0);
                        B1 = __hfma2(wd[25 + k], xk, B1);
                        B2 = __hfma2(wd[50 + k], xk, B2);
                        B3 = __hfma2(wd[75 + k], xk, B3);
                    }
                }

                // fp32 cross-chain combine; lanes = channels (c0, c1)
                float2 a0 = __half22float2(A0), e0 = __half22float2(B0);
                float2 a1 = __half22float2(A1), e1 = __half22float2(B1);
                float2 a2 = __half22float2(A2), e2 = __half22float2(B2);
                float2 a3 = __half22float2(A3), e3 = __half22float2(B3);

                // subpixel u=i*2+j -> (2h+i, 2w+j); channels 2pp, 2pp+1
                float* oC0 = optr + (size_t)(2 * pp) * (128 * 128);
                float* oC1 = oC0 + (128 * 128);
                *reinterpret_cast<float2*>(oC0)       = make_float2(a0.x + e0.x, a1.x + e1.x);
                *reinterpret_cast<float2*>(oC0 + 128) = make_float2(a2.x + e2.x, a3.x + e3.x);
                *reinterpret_cast<float2*>(oC1)       = make_float2(a0.y + e0.y, a1.y + e1.y);
                *reinterpret_cast<float2*>(oC1 + 128) = make_float2(a2.y + e2.y, a3.y + e3.y);
            }
            optr += (size_t)8 * (128 * 128);

            rdF++; if (rdF == NFB) rdF = 0;
        }

        u += cnt; rem -= cnt;
    }
}

extern "C" void kernel_launch(void* const* d_in, const int* in_sizes, int n_in,
                              void* d_out, int out_size)
{
    const float* x  = (const float*)d_in[0];   // [8,256,64,64]
    const float* km = (const float*)d_in[1];   // [8,100,64,64]
    float* out = (float*)d_out;                // [8,256,128,128]

    carafe_kernel<<<NCTA, THREADS>>>(x, km, out);
}